// round 4
// baseline (speedup 1.0000x reference)
#include <cuda_runtime.h>
#include <cuda_fp16.h>
#include <cuda_bf16.h>

#define N_NODES 100000
#define N_EDGES 3200000
#define HID 64
#define SCAN_CHUNK 1024
#define SCAN_BLOCKS ((N_NODES + SCAN_CHUNK - 1) / SCAN_CHUNK)   // 98

// ---------------- scratch (static device globals; no allocation) ----------------
__device__ int          g_is64;
__device__ int          g_cnt[N_NODES];
__device__ int          g_rowptr[N_NODES + 1];
__device__ int          g_cursor[N_NODES];
__device__ int          g_bsum[SCAN_BLOCKS];
__device__ int          g_boff[SCAN_BLOCKS];
__device__ int2         g_edge[N_EDGES];            // {src, bitcast(w)} bucketed by dst
__device__ float        g_a1[N_NODES];              // layer-1 scalar aggregation (atomic)
__device__ unsigned int g_g1h[N_NODES * (HID / 2)]; // h1@W2_rel as half2 (cols 2c,2c+1)
__device__ float4       g_p2[N_NODES * HID / 4];    // b2 + h1@W2_root (fp32)
__device__ float        g_s[N_NODES];               // h2 . W3_rel
__device__ float        g_t[N_NODES];               // h2 . W3_root

// ---- packed f32x2 helpers (Blackwell FFMA2) ----
__device__ __forceinline__ void ffma2(unsigned long long& d,
                                      unsigned long long a,
                                      unsigned long long b) {
    asm("fma.rn.f32x2 %0, %1, %2, %0;" : "+l"(d) : "l"(a), "l"(b));
}
__device__ __forceinline__ unsigned long long pack2(float h) {
    unsigned long long r;
    asm("mov.b64 %0, {%1, %1};" : "=l"(r) : "f"(h));
    return r;
}
__device__ __forceinline__ float2 unpack2(unsigned long long v) {
    float2 f;
    asm("mov.b64 {%0, %1}, %2;" : "=f"(f.x), "=f"(f.y) : "l"(v));
    return f;
}

// ---------------- K0: detect int64 vs int32 edge_index ----------------
__global__ void k_detect(const unsigned int* __restrict__ w) {
    int t = threadIdx.x;
    unsigned int v = 0;
    for (int i = t; i < 1024; i += 32) v |= w[2 * i + 1];
    #pragma unroll
    for (int off = 16; off > 0; off >>= 1)
        v |= __shfl_down_sync(0xFFFFFFFFu, v, off);
    if (t == 0) g_is64 = (v == 0) ? 1 : 0;
}

// ---------------- K1: zero histogram + a1 ----------------
__global__ void k_zero() {
    int i = blockIdx.x * blockDim.x + threadIdx.x;
    if (i < N_NODES) { g_cnt[i] = 0; g_a1[i] = 0.f; }
}

// ---------------- K2: histogram of dst ----------------
__global__ void k_hist(const void* __restrict__ ei_raw) {
    int e = blockIdx.x * blockDim.x + threadIdx.x;
    if (e >= N_EDGES) return;
    int dst;
    if (g_is64) dst = (int)((const long long*)ei_raw)[N_EDGES + e];
    else        dst = ((const int*)ei_raw)[N_EDGES + e];
    atomicAdd(&g_cnt[dst], 1);
}

// ---------------- K3a: per-block exclusive scan ----------------
__global__ void __launch_bounds__(1024) k_scanA() {
    __shared__ int wsum[32];
    int tid = threadIdx.x;
    int i = blockIdx.x * SCAN_CHUNK + tid;
    int lane = tid & 31, wid = tid >> 5;
    int v = (i < N_NODES) ? g_cnt[i] : 0;
    int incl = v;
    #pragma unroll
    for (int off = 1; off < 32; off <<= 1) {
        int n = __shfl_up_sync(0xFFFFFFFFu, incl, off);
        if (lane >= off) incl += n;
    }
    if (lane == 31) wsum[wid] = incl;
    __syncthreads();
    if (wid == 0) {
        int s = wsum[lane];
        int si = s;
        #pragma unroll
        for (int off = 1; off < 32; off <<= 1) {
            int n = __shfl_up_sync(0xFFFFFFFFu, si, off);
            if (lane >= off) si += n;
        }
        wsum[lane] = si - s;
        if (lane == 31) g_bsum[blockIdx.x] = si;
    }
    __syncthreads();
    if (i < N_NODES) g_rowptr[i] = incl - v + wsum[wid];
}

// ---------------- K3b: scan block sums ----------------
__global__ void k_scanB() {
    __shared__ int buf[128];
    int t = threadIdx.x;
    int v = (t < SCAN_BLOCKS) ? g_bsum[t] : 0;
    buf[t] = v;
    __syncthreads();
    int acc = v;
    for (int off = 1; off < 128; off <<= 1) {
        int add = (t >= off) ? buf[t - off] : 0;
        __syncthreads();
        acc += add;
        buf[t] = acc;
        __syncthreads();
    }
    if (t < SCAN_BLOCKS) g_boff[t] = acc - v;
}

// ---------------- K3c: add block offsets, init cursor ----------------
__global__ void k_scanC() {
    int i = blockIdx.x * blockDim.x + threadIdx.x;
    if (i < N_NODES) {
        int r = g_rowptr[i] + g_boff[i / SCAN_CHUNK];
        g_rowptr[i] = r;
        g_cursor[i] = r;
    }
    if (i == 0) g_rowptr[N_NODES] = N_EDGES;
}

// ---------------- K4: scatter edges + fused layer-1 scalar agg ----------------
__global__ void k_scatter(const void* __restrict__ ei_raw,
                          const float* __restrict__ ew,
                          const float* __restrict__ x) {
    int e = blockIdx.x * blockDim.x + threadIdx.x;
    if (e >= N_EDGES) return;
    int src, dst;
    if (g_is64) {
        const long long* ei = (const long long*)ei_raw;
        src = (int)ei[e];
        dst = (int)ei[N_EDGES + e];
    } else {
        const int* ei = (const int*)ei_raw;
        src = ei[e];
        dst = ei[N_EDGES + e];
    }
    float w = ew[e];
    int pos = atomicAdd(&g_cursor[dst], 1);
    g_edge[pos] = make_int2(src, __float_as_int(w));
    atomicAdd(&g_a1[dst], w * __ldg(&x[src]));
}

// ---------------- K5: per-node dense via FFMA2: h1 -> g1h (fp16), p2 (fp32) ----------
__global__ void __launch_bounds__(256) k_dense(
    const float* __restrict__ x,
    const float* __restrict__ W1_rel, const float* __restrict__ b1,
    const float* __restrict__ W1_root,
    const float* __restrict__ W2_rel, const float* __restrict__ b2,
    const float* __restrict__ W2_root)
{
    __shared__ float sW1r[HID], sB1[HID], sW1o[HID], sB2[HID];
    __shared__ float4 sW2r[HID * HID / 4];
    __shared__ float4 sW2o[HID * HID / 4];
    int tid = threadIdx.x;
    if (tid < HID) { sW1r[tid] = W1_rel[tid]; sB1[tid] = b1[tid];
                     sW1o[tid] = W1_root[tid]; sB2[tid] = b2[tid]; }
    for (int k = tid; k < HID * HID / 4; k += 256) {
        sW2r[k] = ((const float4*)W2_rel)[k];
        sW2o[k] = ((const float4*)W2_root)[k];
    }
    __syncthreads();

    int i = blockIdx.x * 256 + tid;
    if (i >= N_NODES) return;
    float xi = x[i];
    float ai = g_a1[i];

    unsigned long long acc[32];   // 32 f32x2 pairs = 64 columns

    // ---- pass A: g1 = h1 @ W2_rel  -> fp16x2
    #pragma unroll
    for (int j = 0; j < 32; j++) acc[j] = 0ull;
    for (int c = 0; c < HID; c++) {
        float h = fmaxf(fmaf(ai, sW1r[c], fmaf(xi, sW1o[c], sB1[c])), 0.f);
        unsigned long long hh = pack2(h);
        const unsigned long long* row =
            (const unsigned long long*)&sW2r[c * (HID / 4)];
        #pragma unroll
        for (int j = 0; j < 32; j++) ffma2(acc[j], row[j], hh);
    }
    {
        unsigned int* out1 = &g_g1h[i * (HID / 2)];
        #pragma unroll
        for (int j = 0; j < 32; j++) {
            float2 f = unpack2(acc[j]);
            __half2 p = __floats2half2_rn(f.x, f.y);
            out1[j] = *(unsigned int*)&p;
        }
    }

    // ---- pass B: p2 = b2 + h1 @ W2_root (fp32)
    #pragma unroll
    for (int j = 0; j < 32; j++) acc[j] = 0ull;
    for (int c = 0; c < HID; c++) {
        float h = fmaxf(fmaf(ai, sW1r[c], fmaf(xi, sW1o[c], sB1[c])), 0.f);
        unsigned long long hh = pack2(h);
        const unsigned long long* row =
            (const unsigned long long*)&sW2o[c * (HID / 4)];
        #pragma unroll
        for (int j = 0; j < 32; j++) ffma2(acc[j], row[j], hh);
    }
    {
        float2* out2 = (float2*)&g_p2[i * (HID / 4)];
        #pragma unroll
        for (int j = 0; j < 32; j++) {
            float2 f = unpack2(acc[j]);
            f.x += sB2[2 * j + 0];
            f.y += sB2[2 * j + 1];
            out2[j] = f;
        }
    }
}

// ---------------- K6: layer-2 wide aggregation (warp/dst, fp16 gather, x4 unroll) -----
__global__ void __launch_bounds__(256) k_agg2(
    const float* __restrict__ W3_rel, const float* __restrict__ W3_root)
{
    __shared__ float sW3r[HID], sW3o[HID];
    int tid = threadIdx.x;
    if (tid < HID) { sW3r[tid] = W3_rel[tid]; sW3o[tid] = W3_root[tid]; }
    __syncthreads();

    int i = (blockIdx.x * 256 + tid) >> 5;
    int lane = tid & 31;
    if (i >= N_NODES) return;
    int beg = g_rowptr[i], end = g_rowptr[i + 1];

    float a0a = 0.f, a1a = 0.f, a0b = 0.f, a1b = 0.f;
    for (int base = beg; base < end; base += 32) {
        int n = end - base; if (n > 32) n = 32;
        int2 ed = (lane < n) ? g_edge[base + lane] : make_int2(0, 0);
        int j = 0;
        for (; j + 4 <= n; j += 4) {
            int   s0 = __shfl_sync(0xFFFFFFFFu, ed.x, j);
            int   s1 = __shfl_sync(0xFFFFFFFFu, ed.x, j + 1);
            int   s2 = __shfl_sync(0xFFFFFFFFu, ed.x, j + 2);
            int   s3 = __shfl_sync(0xFFFFFFFFu, ed.x, j + 3);
            float w0 = __int_as_float(__shfl_sync(0xFFFFFFFFu, ed.y, j));
            float w1 = __int_as_float(__shfl_sync(0xFFFFFFFFu, ed.y, j + 1));
            float w2 = __int_as_float(__shfl_sync(0xFFFFFFFFu, ed.y, j + 2));
            float w3 = __int_as_float(__shfl_sync(0xFFFFFFFFu, ed.y, j + 3));
            unsigned int p0 = __ldg(&g_g1h[s0 * (HID / 2) + lane]);
            unsigned int p1 = __ldg(&g_g1h[s1 * (HID / 2) + lane]);
            unsigned int p2 = __ldg(&g_g1h[s2 * (HID / 2) + lane]);
            unsigned int p3 = __ldg(&g_g1h[s3 * (HID / 2) + lane]);
            float2 f0 = __half22float2(*(__half2*)&p0);
            float2 f1 = __half22float2(*(__half2*)&p1);
            float2 f2 = __half22float2(*(__half2*)&p2);
            float2 f3 = __half22float2(*(__half2*)&p3);
            a0a = fmaf(w0, f0.x, a0a); a1a = fmaf(w0, f0.y, a1a);
            a0b = fmaf(w1, f1.x, a0b); a1b = fmaf(w1, f1.y, a1b);
            a0a = fmaf(w2, f2.x, a0a); a1a = fmaf(w2, f2.y, a1a);
            a0b = fmaf(w3, f3.x, a0b); a1b = fmaf(w3, f3.y, a1b);
        }
        for (; j < n; j++) {
            int   s = __shfl_sync(0xFFFFFFFFu, ed.x, j);
            float w = __int_as_float(__shfl_sync(0xFFFFFFFFu, ed.y, j));
            unsigned int p = __ldg(&g_g1h[s * (HID / 2) + lane]);
            float2 f = __half22float2(*(__half2*)&p);
            a0a = fmaf(w, f.x, a0a); a1a = fmaf(w, f.y, a1a);
        }
    }
    float acc0 = a0a + a0b, acc1 = a1a + a1b;

    const float* p2f = (const float*)g_p2;
    float h0 = fmaxf(acc0 + p2f[i * HID + 2 * lane],     0.f);
    float h1 = fmaxf(acc1 + p2f[i * HID + 2 * lane + 1], 0.f);

    float sp = fmaf(h1, sW3r[2 * lane + 1], h0 * sW3r[2 * lane]);
    float tp = fmaf(h1, sW3o[2 * lane + 1], h0 * sW3o[2 * lane]);
    #pragma unroll
    for (int off = 16; off > 0; off >>= 1) {
        sp += __shfl_down_sync(0xFFFFFFFFu, sp, off);
        tp += __shfl_down_sync(0xFFFFFFFFu, tp, off);
    }
    if (lane == 0) { g_s[i] = sp; g_t[i] = tp; }
}

// ---------------- K7a: out init: out[i] = b3 + t[i] ----------------
__global__ void k_out_init(const float* __restrict__ b3, float* __restrict__ out) {
    int i = blockIdx.x * blockDim.x + threadIdx.x;
    if (i < N_NODES) out[i] = b3[0] + g_t[i];
}

// ---------------- K7b: edge-parallel layer-3 aggregation (REDG) ----------------
__global__ void k_out_edges(const void* __restrict__ ei_raw,
                            const float* __restrict__ ew,
                            float* __restrict__ out) {
    int e = blockIdx.x * blockDim.x + threadIdx.x;
    if (e >= N_EDGES) return;
    int src, dst;
    if (g_is64) {
        const long long* ei = (const long long*)ei_raw;
        src = (int)ei[e];
        dst = (int)ei[N_EDGES + e];
    } else {
        const int* ei = (const int*)ei_raw;
        src = ei[e];
        dst = ei[N_EDGES + e];
    }
    atomicAdd(&out[dst], ew[e] * __ldg(&g_s[src]));
}

// ---------------- launch ----------------
extern "C" void kernel_launch(void* const* d_in, const int* in_sizes, int n_in,
                              void* d_out, int out_size) {
    const float* x       = (const float*)d_in[0];
    const void*  ei_raw  = d_in[1];
    const float* ew      = (const float*)d_in[2];
    const float* W1_rel  = (const float*)d_in[3];
    const float* b1      = (const float*)d_in[4];
    const float* W1_root = (const float*)d_in[5];
    const float* W2_rel  = (const float*)d_in[6];
    const float* b2      = (const float*)d_in[7];
    const float* W2_root = (const float*)d_in[8];
    const float* W3_rel  = (const float*)d_in[9];
    const float* b3      = (const float*)d_in[10];
    const float* W3_root = (const float*)d_in[11];
    float* out = (float*)d_out;

    const int nb_nodes = (N_NODES + 255) / 256;
    const int nb_edges = (N_EDGES + 255) / 256;

    k_detect<<<1, 32>>>((const unsigned int*)ei_raw);
    k_zero<<<nb_nodes, 256>>>();
    k_hist<<<nb_edges, 256>>>(ei_raw);
    k_scanA<<<SCAN_BLOCKS, 1024>>>();
    k_scanB<<<1, 128>>>();
    k_scanC<<<nb_nodes, 256>>>();
    k_scatter<<<nb_edges, 256>>>(ei_raw, ew, x);
    k_dense<<<nb_nodes, 256>>>(x, W1_rel, b1, W1_root, W2_rel, b2, W2_root);
    k_agg2<<<(N_NODES * 32 + 255) / 256, 256>>>(W3_rel, W3_root);
    k_out_init<<<nb_nodes, 256>>>(b3, out);
    k_out_edges<<<nb_edges, 256>>>(ei_raw, ew, out);
}

// round 5
// speedup vs baseline: 1.0333x; 1.0333x over previous
#include <cuda_runtime.h>
#include <cuda_fp16.h>
#include <cuda_bf16.h>

#define N_NODES 100000
#define N_EDGES 3200000
#define HID 64
#define SCAN_CHUNK 1024
#define SCAN_BLOCKS ((N_NODES + SCAN_CHUNK - 1) / SCAN_CHUNK)   // 98

// ---------------- scratch (static device globals; no allocation) ----------------
__device__ int          g_is64;
__device__ int          g_cnt[N_NODES];
__device__ int          g_rowptr[N_NODES + 1];
__device__ int          g_cursor[N_NODES];
__device__ int          g_bsum[SCAN_BLOCKS];
__device__ int          g_boff[SCAN_BLOCKS];
__device__ int2         g_edge[N_EDGES];            // {src, bitcast(w)} bucketed by dst
__device__ float        g_a1[N_NODES];              // layer-1 scalar aggregation (atomic)
__device__ unsigned int g_g1h[N_NODES * (HID / 2)]; // h1@W2_rel as half2 (cols 2c,2c+1)
__device__ float4       g_p2[N_NODES * HID / 4];    // b2 + h1@W2_root (fp32)
__device__ float        g_s[N_NODES];               // h2 . W3_rel
__device__ float        g_t[N_NODES];               // h2 . W3_root

// ---------------- K1: zero histogram + a1, block 0 warp 0 also detects dtype --------
__global__ void k_init(const unsigned int* __restrict__ w) {
    int i = blockIdx.x * blockDim.x + threadIdx.x;
    if (i < N_NODES) { g_cnt[i] = 0; g_a1[i] = 0.f; }
    if (blockIdx.x == 0 && threadIdx.x < 32) {
        int t = threadIdx.x;
        unsigned int v = 0;
        for (int k = t; k < 1024; k += 32) v |= w[2 * k + 1];
        #pragma unroll
        for (int off = 16; off > 0; off >>= 1)
            v |= __shfl_down_sync(0xFFFFFFFFu, v, off);
        if (t == 0) g_is64 = (v == 0) ? 1 : 0;
    }
}

// ---------------- K2: histogram of dst ----------------
__global__ void k_hist(const void* __restrict__ ei_raw) {
    int e = blockIdx.x * blockDim.x + threadIdx.x;
    if (e >= N_EDGES) return;
    int dst;
    if (g_is64) dst = (int)((const long long*)ei_raw)[N_EDGES + e];
    else        dst = ((const int*)ei_raw)[N_EDGES + e];
    atomicAdd(&g_cnt[dst], 1);
}

// ---------------- K3a: per-block exclusive scan ----------------
__global__ void __launch_bounds__(1024) k_scanA() {
    __shared__ int wsum[32];
    int tid = threadIdx.x;
    int i = blockIdx.x * SCAN_CHUNK + tid;
    int lane = tid & 31, wid = tid >> 5;
    int v = (i < N_NODES) ? g_cnt[i] : 0;
    int incl = v;
    #pragma unroll
    for (int off = 1; off < 32; off <<= 1) {
        int n = __shfl_up_sync(0xFFFFFFFFu, incl, off);
        if (lane >= off) incl += n;
    }
    if (lane == 31) wsum[wid] = incl;
    __syncthreads();
    if (wid == 0) {
        int s = wsum[lane];
        int si = s;
        #pragma unroll
        for (int off = 1; off < 32; off <<= 1) {
            int n = __shfl_up_sync(0xFFFFFFFFu, si, off);
            if (lane >= off) si += n;
        }
        wsum[lane] = si - s;
        if (lane == 31) g_bsum[blockIdx.x] = si;
    }
    __syncthreads();
    if (i < N_NODES) g_rowptr[i] = incl - v + wsum[wid];
}

// ---------------- K3b: scan block sums ----------------
__global__ void k_scanB() {
    __shared__ int buf[128];
    int t = threadIdx.x;
    int v = (t < SCAN_BLOCKS) ? g_bsum[t] : 0;
    buf[t] = v;
    __syncthreads();
    int acc = v;
    for (int off = 1; off < 128; off <<= 1) {
        int add = (t >= off) ? buf[t - off] : 0;
        __syncthreads();
        acc += add;
        buf[t] = acc;
        __syncthreads();
    }
    if (t < SCAN_BLOCKS) g_boff[t] = acc - v;
}

// ---------------- K3c: add block offsets, init cursor ----------------
__global__ void k_scanC() {
    int i = blockIdx.x * blockDim.x + threadIdx.x;
    if (i < N_NODES) {
        int r = g_rowptr[i] + g_boff[i / SCAN_CHUNK];
        g_rowptr[i] = r;
        g_cursor[i] = r;
    }
    if (i == 0) g_rowptr[N_NODES] = N_EDGES;
}

// ---------------- K4: scatter edges + fused layer-1 scalar agg ----------------
__global__ void k_scatter(const void* __restrict__ ei_raw,
                          const float* __restrict__ ew,
                          const float* __restrict__ x) {
    int e = blockIdx.x * blockDim.x + threadIdx.x;
    if (e >= N_EDGES) return;
    int src, dst;
    if (g_is64) {
        const long long* ei = (const long long*)ei_raw;
        src = (int)ei[e];
        dst = (int)ei[N_EDGES + e];
    } else {
        const int* ei = (const int*)ei_raw;
        src = ei[e];
        dst = ei[N_EDGES + e];
    }
    float w = ew[e];
    int pos = atomicAdd(&g_cursor[dst], 1);
    g_edge[pos] = make_int2(src, __float_as_int(w));
    atomicAdd(&g_a1[dst], w * __ldg(&x[src]));
}

// ---------------- K5: per-node dense (float4): h1 -> g1h (fp16), p2 (fp32) ----------
__global__ void __launch_bounds__(256) k_dense(
    const float* __restrict__ x,
    const float* __restrict__ W1_rel, const float* __restrict__ b1,
    const float* __restrict__ W1_root,
    const float* __restrict__ W2_rel, const float* __restrict__ b2,
    const float* __restrict__ W2_root)
{
    __shared__ float sW1r[HID], sB1[HID], sW1o[HID], sB2[HID];
    __shared__ float4 sW2r[HID * HID / 4];
    __shared__ float4 sW2o[HID * HID / 4];
    int tid = threadIdx.x;
    if (tid < HID) { sW1r[tid] = W1_rel[tid]; sB1[tid] = b1[tid];
                     sW1o[tid] = W1_root[tid]; sB2[tid] = b2[tid]; }
    for (int k = tid; k < HID * HID / 4; k += 256) {
        sW2r[k] = ((const float4*)W2_rel)[k];
        sW2o[k] = ((const float4*)W2_root)[k];
    }
    __syncthreads();

    int i = blockIdx.x * 256 + tid;
    if (i >= N_NODES) return;
    float xi = x[i];
    float ai = g_a1[i];

    float4 acc[16];
    // ---- pass A: g1 = h1 @ W2_rel  -> fp16x2
    #pragma unroll
    for (int j = 0; j < 16; j++) acc[j] = make_float4(0.f, 0.f, 0.f, 0.f);
    for (int c = 0; c < HID; c++) {
        float h = fmaxf(fmaf(ai, sW1r[c], fmaf(xi, sW1o[c], sB1[c])), 0.f);
        const float4* row = &sW2r[c * (HID / 4)];
        #pragma unroll
        for (int j = 0; j < 16; j++) {
            float4 w = row[j];
            acc[j].x = fmaf(h, w.x, acc[j].x);
            acc[j].y = fmaf(h, w.y, acc[j].y);
            acc[j].z = fmaf(h, w.z, acc[j].z);
            acc[j].w = fmaf(h, w.w, acc[j].w);
        }
    }
    {
        unsigned int* out1 = &g_g1h[i * (HID / 2)];
        #pragma unroll
        for (int j = 0; j < 16; j++) {
            __half2 p0 = __floats2half2_rn(acc[j].x, acc[j].y);
            __half2 p1 = __floats2half2_rn(acc[j].z, acc[j].w);
            out1[j * 2 + 0] = *(unsigned int*)&p0;
            out1[j * 2 + 1] = *(unsigned int*)&p1;
        }
    }
    // ---- pass B: p2 = b2 + h1 @ W2_root (fp32)
    #pragma unroll
    for (int j = 0; j < 16; j++) acc[j] = make_float4(0.f, 0.f, 0.f, 0.f);
    for (int c = 0; c < HID; c++) {
        float h = fmaxf(fmaf(ai, sW1r[c], fmaf(xi, sW1o[c], sB1[c])), 0.f);
        const float4* row = &sW2o[c * (HID / 4)];
        #pragma unroll
        for (int j = 0; j < 16; j++) {
            float4 w = row[j];
            acc[j].x = fmaf(h, w.x, acc[j].x);
            acc[j].y = fmaf(h, w.y, acc[j].y);
            acc[j].z = fmaf(h, w.z, acc[j].z);
            acc[j].w = fmaf(h, w.w, acc[j].w);
        }
    }
    {
        float4* out2 = &g_p2[i * (HID / 4)];
        #pragma unroll
        for (int j = 0; j < 16; j++) {
            float4 v = acc[j];
            v.x += sB2[j * 4 + 0];
            v.y += sB2[j * 4 + 1];
            v.z += sB2[j * 4 + 2];
            v.w += sB2[j * 4 + 3];
            out2[j] = v;
        }
    }
}

// ---------------- K6: layer-2 wide aggregation (warp/dst, fp16 gather, x8 unroll) -----
__global__ void __launch_bounds__(256) k_agg2(
    const float* __restrict__ W3_rel, const float* __restrict__ W3_root)
{
    __shared__ float sW3r[HID], sW3o[HID];
    int tid = threadIdx.x;
    if (tid < HID) { sW3r[tid] = W3_rel[tid]; sW3o[tid] = W3_root[tid]; }
    __syncthreads();

    int i = (blockIdx.x * 256 + tid) >> 5;
    int lane = tid & 31;
    if (i >= N_NODES) return;
    int beg = g_rowptr[i], end = g_rowptr[i + 1];

    float a0a = 0.f, a1a = 0.f, a0b = 0.f, a1b = 0.f;
    for (int base = beg; base < end; base += 32) {
        int n = end - base; if (n > 32) n = 32;
        int2 ed = (lane < n) ? g_edge[base + lane] : make_int2(0, 0);
        int j = 0;
        for (; j + 8 <= n; j += 8) {
            unsigned int p[8];
            float w[8];
            #pragma unroll
            for (int k = 0; k < 8; k++) {
                int   s = __shfl_sync(0xFFFFFFFFu, ed.x, j + k);
                w[k] = __int_as_float(__shfl_sync(0xFFFFFFFFu, ed.y, j + k));
                p[k] = __ldg(&g_g1h[s * (HID / 2) + lane]);
            }
            #pragma unroll
            for (int k = 0; k < 8; k++) {
                float2 f = __half22float2(*(__half2*)&p[k]);
                if (k & 1) { a0b = fmaf(w[k], f.x, a0b); a1b = fmaf(w[k], f.y, a1b); }
                else       { a0a = fmaf(w[k], f.x, a0a); a1a = fmaf(w[k], f.y, a1a); }
            }
        }
        for (; j < n; j++) {
            int   s = __shfl_sync(0xFFFFFFFFu, ed.x, j);
            float w = __int_as_float(__shfl_sync(0xFFFFFFFFu, ed.y, j));
            unsigned int p = __ldg(&g_g1h[s * (HID / 2) + lane]);
            float2 f = __half22float2(*(__half2*)&p);
            a0a = fmaf(w, f.x, a0a); a1a = fmaf(w, f.y, a1a);
        }
    }
    float acc0 = a0a + a0b, acc1 = a1a + a1b;

    const float* p2f = (const float*)g_p2;
    float h0 = fmaxf(acc0 + p2f[i * HID + 2 * lane],     0.f);
    float h1 = fmaxf(acc1 + p2f[i * HID + 2 * lane + 1], 0.f);

    float sp = fmaf(h1, sW3r[2 * lane + 1], h0 * sW3r[2 * lane]);
    float tp = fmaf(h1, sW3o[2 * lane + 1], h0 * sW3o[2 * lane]);
    #pragma unroll
    for (int off = 16; off > 0; off >>= 1) {
        sp += __shfl_down_sync(0xFFFFFFFFu, sp, off);
        tp += __shfl_down_sync(0xFFFFFFFFu, tp, off);
    }
    if (lane == 0) { g_s[i] = sp; g_t[i] = tp; }
}

// ---------------- K7: layer-3 scalar aggregation, warp per dst -> out ----------------
__global__ void __launch_bounds__(256) k_out(const float* __restrict__ b3,
                                             float* __restrict__ out) {
    int i = (blockIdx.x * 256 + threadIdx.x) >> 5;
    int lane = threadIdx.x & 31;
    if (i >= N_NODES) return;
    int beg = g_rowptr[i], end = g_rowptr[i + 1];
    float acc = 0.f;
    for (int e = beg + lane; e < end; e += 32) {
        int2 ed = g_edge[e];                        // coalesced within warp
        acc = fmaf(__int_as_float(ed.y), __ldg(&g_s[ed.x]), acc);
    }
    #pragma unroll
    for (int off = 16; off > 0; off >>= 1)
        acc += __shfl_down_sync(0xFFFFFFFFu, acc, off);
    if (lane == 0) out[i] = acc + b3[0] + g_t[i];
}

// ---------------- launch ----------------
extern "C" void kernel_launch(void* const* d_in, const int* in_sizes, int n_in,
                              void* d_out, int out_size) {
    const float* x       = (const float*)d_in[0];
    const void*  ei_raw  = d_in[1];
    const float* ew      = (const float*)d_in[2];
    const float* W1_rel  = (const float*)d_in[3];
    const float* b1      = (const float*)d_in[4];
    const float* W1_root = (const float*)d_in[5];
    const float* W2_rel  = (const float*)d_in[6];
    const float* b2      = (const float*)d_in[7];
    const float* W2_root = (const float*)d_in[8];
    const float* W3_rel  = (const float*)d_in[9];
    const float* b3      = (const float*)d_in[10];
    const float* W3_root = (const float*)d_in[11];
    float* out = (float*)d_out;

    const int nb_nodes = (N_NODES + 255) / 256;
    const int nb_edges = (N_EDGES + 255) / 256;

    k_init<<<nb_nodes, 256>>>((const unsigned int*)ei_raw);
    k_hist<<<nb_edges, 256>>>(ei_raw);
    k_scanA<<<SCAN_BLOCKS, 1024>>>();
    k_scanB<<<1, 128>>>();
    k_scanC<<<nb_nodes, 256>>>();
    k_scatter<<<nb_edges, 256>>>(ei_raw, ew, x);
    k_dense<<<nb_nodes, 256>>>(x, W1_rel, b1, W1_root, W2_rel, b2, W2_root);
    k_agg2<<<(N_NODES * 32 + 255) / 256, 256>>>(W3_rel, W3_root);
    k_out<<<(N_NODES * 32 + 255) / 256, 256>>>(b3, out);
}

// round 6
// speedup vs baseline: 1.0602x; 1.0260x over previous
#include <cuda_runtime.h>
#include <cuda_fp16.h>
#include <cuda_bf16.h>

#define N_NODES 100000
#define N_EDGES 3200000
#define HID 64
#define SCAN_CHUNK 1024
#define SCAN_BLOCKS ((N_NODES + SCAN_CHUNK - 1) / SCAN_CHUNK)   // 98

// ---------------- scratch (static device globals; no allocation) ----------------
__device__ int          g_is64;
__device__ int          g_cnt[N_NODES];
__device__ int          g_rowptr[N_NODES + 1];
__device__ int          g_cursor[N_NODES];
__device__ int          g_bsum[SCAN_BLOCKS];
__device__ int2         g_edge[N_EDGES];            // {src, bitcast(w)} bucketed by dst
__device__ float        g_a1[N_NODES];              // layer-1 scalar aggregation (atomic)
__device__ unsigned int g_g1h[N_NODES * (HID / 2)]; // h1@W2_rel as half2 (cols 2c,2c+1)
__device__ float4       g_p2[N_NODES * HID / 4];    // b2 + h1@W2_root (fp32)
__device__ float        g_s[N_NODES];               // h2 . W3_rel
__device__ float        g_t[N_NODES];               // h2 . W3_root

// ---- packed f32x2 helpers (Blackwell FFMA2) ----
__device__ __forceinline__ void ffma2(unsigned long long& d,
                                      unsigned long long a,
                                      unsigned long long b) {
    asm("fma.rn.f32x2 %0, %1, %2, %0;" : "+l"(d) : "l"(a), "l"(b));
}
__device__ __forceinline__ unsigned long long pack2(float h) {
    unsigned long long r;
    asm("mov.b64 %0, {%1, %1};" : "=l"(r) : "f"(h));
    return r;
}
__device__ __forceinline__ float2 unpack2(unsigned long long v) {
    float2 f;
    asm("mov.b64 {%0, %1}, %2;" : "=f"(f.x), "=f"(f.y) : "l"(v));
    return f;
}

// ---------------- K1: zero histogram + a1, block 0 warp 0 also detects dtype --------
__global__ void k_init(const unsigned int* __restrict__ w) {
    int i = blockIdx.x * blockDim.x + threadIdx.x;
    if (i < N_NODES) { g_cnt[i] = 0; g_a1[i] = 0.f; }
    if (blockIdx.x == 0 && threadIdx.x < 32) {
        int t = threadIdx.x;
        unsigned int v = 0;
        for (int k = t; k < 1024; k += 32) v |= w[2 * k + 1];
        #pragma unroll
        for (int off = 16; off > 0; off >>= 1)
            v |= __shfl_down_sync(0xFFFFFFFFu, v, off);
        if (t == 0) g_is64 = (v == 0) ? 1 : 0;
    }
}

// ---------------- K2: histogram of dst, 4 edges per thread ----------------
__global__ void k_hist(const void* __restrict__ ei_raw) {
    int e0 = (blockIdx.x * blockDim.x + threadIdx.x) * 4;
    if (e0 >= N_EDGES) return;
    int d0, d1, d2, d3;
    if (g_is64) {
        const longlong2* p = (const longlong2*)((const long long*)ei_raw + N_EDGES);
        longlong2 a = p[e0 / 2], b = p[e0 / 2 + 1];
        d0 = (int)a.x; d1 = (int)a.y; d2 = (int)b.x; d3 = (int)b.y;
    } else {
        int4 a = ((const int4*)((const int*)ei_raw + N_EDGES))[e0 / 4];
        d0 = a.x; d1 = a.y; d2 = a.z; d3 = a.w;
    }
    atomicAdd(&g_cnt[d0], 1);
    atomicAdd(&g_cnt[d1], 1);
    atomicAdd(&g_cnt[d2], 1);
    atomicAdd(&g_cnt[d3], 1);
}

// ---------------- K3a: per-block exclusive scan ----------------
__global__ void __launch_bounds__(1024) k_scanA() {
    __shared__ int wsum[32];
    int tid = threadIdx.x;
    int i = blockIdx.x * SCAN_CHUNK + tid;
    int lane = tid & 31, wid = tid >> 5;
    int v = (i < N_NODES) ? g_cnt[i] : 0;
    int incl = v;
    #pragma unroll
    for (int off = 1; off < 32; off <<= 1) {
        int n = __shfl_up_sync(0xFFFFFFFFu, incl, off);
        if (lane >= off) incl += n;
    }
    if (lane == 31) wsum[wid] = incl;
    __syncthreads();
    if (wid == 0) {
        int s = wsum[lane];
        int si = s;
        #pragma unroll
        for (int off = 1; off < 32; off <<= 1) {
            int n = __shfl_up_sync(0xFFFFFFFFu, si, off);
            if (lane >= off) si += n;
        }
        wsum[lane] = si - s;
        if (lane == 31) g_bsum[blockIdx.x] = si;
    }
    __syncthreads();
    if (i < N_NODES) g_rowptr[i] = incl - v + wsum[wid];
}

// ---------------- K3b: add chunk offsets (derived in-block), init cursor ------------
__global__ void __launch_bounds__(256) k_scanC() {
    __shared__ int s_off;
    int tid = threadIdx.x;
    int cid = blockIdx.x >> 2;            // 256-thread block sits inside one 1024-chunk
    // warp 0 sums bsum[0..cid)
    if (tid < 32) {
        int acc = 0;
        for (int k = tid; k < cid; k += 32) acc += g_bsum[k];
        #pragma unroll
        for (int off = 16; off > 0; off >>= 1)
            acc += __shfl_down_sync(0xFFFFFFFFu, acc, off);
        if (tid == 0) s_off = acc;
    }
    __syncthreads();
    int i = blockIdx.x * 256 + tid;
    if (i < N_NODES) {
        int r = g_rowptr[i] + s_off;
        g_rowptr[i] = r;
        g_cursor[i] = r;
    }
    if (i == 0) g_rowptr[N_NODES] = N_EDGES;
}

// ---------------- K4: scatter edges + fused layer-1 agg, 2 edges per thread ---------
__global__ void k_scatter(const void* __restrict__ ei_raw,
                          const float* __restrict__ ew,
                          const float* __restrict__ x) {
    int e0 = (blockIdx.x * blockDim.x + threadIdx.x) * 2;
    if (e0 >= N_EDGES) return;
    int s0, s1, d0, d1;
    if (g_is64) {
        const long long* ei = (const long long*)ei_raw;
        longlong2 sp = ((const longlong2*)ei)[e0 / 2];
        longlong2 dp = ((const longlong2*)(ei + N_EDGES))[e0 / 2];
        s0 = (int)sp.x; s1 = (int)sp.y; d0 = (int)dp.x; d1 = (int)dp.y;
    } else {
        const int* ei = (const int*)ei_raw;
        int2 sp = ((const int2*)ei)[e0 / 2];
        int2 dp = ((const int2*)(ei + N_EDGES))[e0 / 2];
        s0 = sp.x; s1 = sp.y; d0 = dp.x; d1 = dp.y;
    }
    float2 w = ((const float2*)ew)[e0 / 2];
    float x0 = __ldg(&x[s0]);
    float x1 = __ldg(&x[s1]);
    int p0 = atomicAdd(&g_cursor[d0], 1);
    int p1 = atomicAdd(&g_cursor[d1], 1);
    g_edge[p0] = make_int2(s0, __float_as_int(w.x));
    g_edge[p1] = make_int2(s1, __float_as_int(w.y));
    atomicAdd(&g_a1[d0], w.x * x0);
    atomicAdd(&g_a1[d1], w.y * x1);
}

// ---------------- K5: per-node dense via FFMA2: h1 -> g1h (fp16), p2 (fp32) ---------
__global__ void __launch_bounds__(256) k_dense(
    const float* __restrict__ x,
    const float* __restrict__ W1_rel, const float* __restrict__ b1,
    const float* __restrict__ W1_root,
    const float* __restrict__ W2_rel, const float* __restrict__ b2,
    const float* __restrict__ W2_root)
{
    __shared__ float sW1r[HID], sB1[HID], sW1o[HID], sB2[HID];
    __shared__ float4 sW2r[HID * HID / 4];
    __shared__ float4 sW2o[HID * HID / 4];
    int tid = threadIdx.x;
    if (tid < HID) { sW1r[tid] = W1_rel[tid]; sB1[tid] = b1[tid];
                     sW1o[tid] = W1_root[tid]; sB2[tid] = b2[tid]; }
    for (int k = tid; k < HID * HID / 4; k += 256) {
        sW2r[k] = ((const float4*)W2_rel)[k];
        sW2o[k] = ((const float4*)W2_root)[k];
    }
    __syncthreads();

    int i = blockIdx.x * 256 + tid;
    if (i >= N_NODES) return;
    float xi = x[i];
    float ai = g_a1[i];

    unsigned long long acc[32];   // 32 f32x2 pairs = 64 columns

    // ---- pass A: g1 = h1 @ W2_rel  -> fp16x2
    #pragma unroll
    for (int j = 0; j < 32; j++) acc[j] = 0ull;
    for (int c = 0; c < HID; c++) {
        float h = fmaxf(fmaf(ai, sW1r[c], fmaf(xi, sW1o[c], sB1[c])), 0.f);
        unsigned long long hh = pack2(h);
        const unsigned long long* row =
            (const unsigned long long*)&sW2r[c * (HID / 4)];
        #pragma unroll
        for (int j = 0; j < 32; j++) ffma2(acc[j], row[j], hh);
    }
    {
        unsigned int* out1 = &g_g1h[i * (HID / 2)];
        #pragma unroll
        for (int j = 0; j < 32; j++) {
            float2 f = unpack2(acc[j]);
            __half2 p = __floats2half2_rn(f.x, f.y);
            out1[j] = *(unsigned int*)&p;
        }
    }

    // ---- pass B: p2 = b2 + h1 @ W2_root (fp32)
    #pragma unroll
    for (int j = 0; j < 32; j++) acc[j] = 0ull;
    for (int c = 0; c < HID; c++) {
        float h = fmaxf(fmaf(ai, sW1r[c], fmaf(xi, sW1o[c], sB1[c])), 0.f);
        unsigned long long hh = pack2(h);
        const unsigned long long* row =
            (const unsigned long long*)&sW2o[c * (HID / 4)];
        #pragma unroll
        for (int j = 0; j < 32; j++) ffma2(acc[j], row[j], hh);
    }
    {
        float2* out2 = (float2*)&g_p2[i * (HID / 4)];
        #pragma unroll
        for (int j = 0; j < 32; j++) {
            float2 f = unpack2(acc[j]);
            f.x += sB2[2 * j + 0];
            f.y += sB2[2 * j + 1];
            out2[j] = f;
        }
    }
}

// ---------------- K6: layer-2 wide aggregation (warp/dst, fp16 gather, x8 unroll) -----
__global__ void __launch_bounds__(256) k_agg2(
    const float* __restrict__ W3_rel, const float* __restrict__ W3_root)
{
    __shared__ float sW3r[HID], sW3o[HID];
    int tid = threadIdx.x;
    if (tid < HID) { sW3r[tid] = W3_rel[tid]; sW3o[tid] = W3_root[tid]; }
    __syncthreads();

    int i = (blockIdx.x * 256 + tid) >> 5;
    int lane = tid & 31;
    if (i >= N_NODES) return;
    int beg = g_rowptr[i], end = g_rowptr[i + 1];

    float a0a = 0.f, a1a = 0.f, a0b = 0.f, a1b = 0.f;
    for (int base = beg; base < end; base += 32) {
        int n = end - base; if (n > 32) n = 32;
        int2 ed = (lane < n) ? g_edge[base + lane] : make_int2(0, 0);
        int j = 0;
        for (; j + 8 <= n; j += 8) {
            unsigned int p[8];
            float w[8];
            #pragma unroll
            for (int k = 0; k < 8; k++) {
                int   s = __shfl_sync(0xFFFFFFFFu, ed.x, j + k);
                w[k] = __int_as_float(__shfl_sync(0xFFFFFFFFu, ed.y, j + k));
                p[k] = __ldg(&g_g1h[s * (HID / 2) + lane]);
            }
            #pragma unroll
            for (int k = 0; k < 8; k++) {
                float2 f = __half22float2(*(__half2*)&p[k]);
                if (k & 1) { a0b = fmaf(w[k], f.x, a0b); a1b = fmaf(w[k], f.y, a1b); }
                else       { a0a = fmaf(w[k], f.x, a0a); a1a = fmaf(w[k], f.y, a1a); }
            }
        }
        for (; j < n; j++) {
            int   s = __shfl_sync(0xFFFFFFFFu, ed.x, j);
            float w = __int_as_float(__shfl_sync(0xFFFFFFFFu, ed.y, j));
            unsigned int p = __ldg(&g_g1h[s * (HID / 2) + lane]);
            float2 f = __half22float2(*(__half2*)&p);
            a0a = fmaf(w, f.x, a0a); a1a = fmaf(w, f.y, a1a);
        }
    }
    float acc0 = a0a + a0b, acc1 = a1a + a1b;

    const float* p2f = (const float*)g_p2;
    float h0 = fmaxf(acc0 + p2f[i * HID + 2 * lane],     0.f);
    float h1 = fmaxf(acc1 + p2f[i * HID + 2 * lane + 1], 0.f);

    float sp = fmaf(h1, sW3r[2 * lane + 1], h0 * sW3r[2 * lane]);
    float tp = fmaf(h1, sW3o[2 * lane + 1], h0 * sW3o[2 * lane]);
    #pragma unroll
    for (int off = 16; off > 0; off >>= 1) {
        sp += __shfl_down_sync(0xFFFFFFFFu, sp, off);
        tp += __shfl_down_sync(0xFFFFFFFFu, tp, off);
    }
    if (lane == 0) { g_s[i] = sp; g_t[i] = tp; }
}

// ---------------- K7: layer-3 scalar aggregation, warp per dst -> out ----------------
__global__ void __launch_bounds__(256) k_out(const float* __restrict__ b3,
                                             float* __restrict__ out) {
    int i = (blockIdx.x * 256 + threadIdx.x) >> 5;
    int lane = threadIdx.x & 31;
    if (i >= N_NODES) return;
    int beg = g_rowptr[i], end = g_rowptr[i + 1];
    float acc = 0.f;
    for (int e = beg + lane; e < end; e += 32) {
        int2 ed = g_edge[e];                        // coalesced within warp
        acc = fmaf(__int_as_float(ed.y), __ldg(&g_s[ed.x]), acc);
    }
    #pragma unroll
    for (int off = 16; off > 0; off >>= 1)
        acc += __shfl_down_sync(0xFFFFFFFFu, acc, off);
    if (lane == 0) out[i] = acc + b3[0] + g_t[i];
}

// ---------------- launch ----------------
extern "C" void kernel_launch(void* const* d_in, const int* in_sizes, int n_in,
                              void* d_out, int out_size) {
    const float* x       = (const float*)d_in[0];
    const void*  ei_raw  = d_in[1];
    const float* ew      = (const float*)d_in[2];
    const float* W1_rel  = (const float*)d_in[3];
    const float* b1      = (const float*)d_in[4];
    const float* W1_root = (const float*)d_in[5];
    const float* W2_rel  = (const float*)d_in[6];
    const float* b2      = (const float*)d_in[7];
    const float* W2_root = (const float*)d_in[8];
    const float* W3_rel  = (const float*)d_in[9];
    const float* b3      = (const float*)d_in[10];
    const float* W3_root = (const float*)d_in[11];
    float* out = (float*)d_out;

    const int nb_nodes = (N_NODES + 255) / 256;

    k_init<<<nb_nodes, 256>>>((const unsigned int*)ei_raw);
    k_hist<<<(N_EDGES / 4 + 255) / 256, 256>>>(ei_raw);
    k_scanA<<<SCAN_BLOCKS, 1024>>>();
    k_scanC<<<nb_nodes, 256>>>();
    k_scatter<<<(N_EDGES / 2 + 255) / 256, 256>>>(ei_raw, ew, x);
    k_dense<<<nb_nodes, 256>>>(x, W1_rel, b1, W1_root, W2_rel, b2, W2_root);
    k_agg2<<<(N_NODES * 32 + 255) / 256, 256>>>(W3_rel, W3_root);
    k_out<<<(N_NODES * 32 + 255) / 256, 256>>>(b3, out);
}